// round 13
// baseline (speedup 1.0000x reference)
#include <cuda_runtime.h>
#include <cuda_fp16.h>
#include <math.h>

#define NB     96
#define NP     97           // smem stride (conflict-free)
#define N2     (96*96)
#define N4     (96*96*96*96)
#define NPAIR  4656         // #(p<=q)
#define NCHUNK 582          // NPAIR/8 H2x4 chunks per row
#define MMAX   16
#define NITERS_EFF 4        // SCF steps (iters 0..3)

// persistent scratch (allowed: __device__ globals)
__device__ __half g_M[(size_t)NPAIR * NPAIR];  // 43.4 MB packed both ways
__device__ __align__(16) float g_Dpk[NPAIR];   // packed c_r*c_s (r<=s)
__device__ float  g_Fd[NPAIR];
__device__ float  g_c2[NB];
__device__ unsigned g_cnt;                     // last-block counter (monotonic)

struct alignas(16) H2x4 { __half2 h[4]; };

__host__ __device__ __forceinline__ int pair_off(int p) {
    return p * 96 - (p * (p - 1)) / 2;   // index of (p,p) in packed order
}
__device__ __forceinline__ int pair_row(int t) {   // invert pair_off
    int r = (int)((193.0f - sqrtf(193.0f * 193.0f - 8.0f * (float)t)) * 0.5f);
    while (pair_off(r + 1) <= t) ++r;
    while (pair_off(r) > t) --r;
    return r;
}

// ---------------------------------------------------------------------------
// Register-operator matvec (R11 version): dst = Reg-matrix * src (src in smem).
// thread = (row = tid>>2, part = tid&3); Reg holds Mat[row][part*24 .. +24].
// ---------------------------------------------------------------------------
__device__ __forceinline__ void opmv_reg(float* __restrict__ dst,
                                         const float (&Reg)[24],
                                         const float* __restrict__ src,
                                         int row, int jb, int part) {
    float s = 0.f;
#pragma unroll
    for (int j = 0; j < 24; ++j) s = fmaf(Reg[j], src[jb + j], s);
    s += __shfl_xor_sync(0xffffffffu, s, 1);
    s += __shfl_xor_sync(0xffffffffu, s, 2);
    if (part == 0) dst[row] = s;
}

// ---------------------------------------------------------------------------
// Shared-memory block for the solve (~8.7 KB)
// ---------------------------------------------------------------------------
struct SolveSmem {
    float sV[MMAX * NP];
    float sw[96], st1[96], st2[96];
    float sdots[96];
    float salpha[MMAX], sbeta[MMAX], sy[MMAX];
    float sc2[96], sc[96];
    float sctrl[16], sred[16];
};

__device__ void solve_body(SolveSmem* S,
                           const float* __restrict__ gH,
                           const float* __restrict__ gA,
                           const float* __restrict__ gEnuc,
                           float* __restrict__ out, int iter, int tid) {
    const int row = tid >> 2, part = tid & 3, jb = part * 24;

    // ---- load A and F = H (+ Fd) into registers ----
    float Areg[24], Freg[24];
    {
        const float* ga = gA + row * 96 + jb;
        const float* gh = gH + row * 96 + jb;
#pragma unroll
        for (int j = 0; j < 24; ++j) Areg[j] = ga[j];
        if (iter > 0) {
#pragma unroll
            for (int j = 0; j < 24; ++j) {
                const int col = jb + j;
                const int a = row < col ? row : col, b = row < col ? col : row;
                Freg[j] = gh[j] + g_Fd[pair_off(a) + (b - a)];
            }
        } else {
#pragma unroll
            for (int j = 0; j < 24; ++j) Freg[j] = gh[j];
        }
    }

    const int m      = (iter == 0) ? 16 : ((iter == NITERS_EFF - 1) ? 9 : 6);
    const int passes = (iter == 0) ? 2 : 1;

    if (tid < 96) {
        float v;
        if (iter == 0) {
            unsigned h = (unsigned)tid * 2654435761u + 12345u;
            h ^= h >> 13; h *= 0x85ebca6bu; h ^= h >> 16;
            v = (float)(h & 0xFFFFu) * (1.f / 65536.f) - 0.5f;
        } else {
            v = g_c2[tid];
        }
        S->sV[tid] = v;
    }
    __syncthreads();
    if (tid < 32) {
        float s = S->sV[tid] * S->sV[tid] + S->sV[tid + 32] * S->sV[tid + 32]
                + S->sV[tid + 64] * S->sV[tid + 64];
#pragma unroll
        for (int o = 16; o; o >>= 1) s += __shfl_xor_sync(0xffffffffu, s, o);
        if (tid == 0) S->sctrl[0] = rsqrtf(fmaxf(s, 1e-30f));
    }
    __syncthreads();
    if (tid < 96) S->sV[tid] *= S->sctrl[0];
    __syncthreads();

    int meff = m;
    for (int k = 0; k < m; ++k) {
        opmv_reg(S->st1, Areg, S->sV + k * NP, row, jb, part);
        __syncthreads();
        opmv_reg(S->st2, Freg, S->st1, row, jb, part);
        __syncthreads();
        opmv_reg(S->sw, Areg, S->st2, row, jb, part);
        __syncthreads();

#pragma unroll 1
        for (int pass = 0; pass < passes; ++pass) {
            {
                const int j = tid >> 2;
                float s = 0.f;
                if (j <= k) {
#pragma unroll
                    for (int i = 0; i < 24; ++i)
                        s = fmaf(S->sV[j * NP + jb + i], S->sw[jb + i], s);
                }
                s += __shfl_xor_sync(0xffffffffu, s, 1);
                s += __shfl_xor_sync(0xffffffffu, s, 2);
                if (part == 0 && j <= k) S->sdots[j] = s;
            }
            __syncthreads();
            if (pass == 0 && tid == 0) S->salpha[k] = S->sdots[k];
            if (tid < 96) {
                float wi = S->sw[tid];
                for (int j = 0; j <= k; ++j) wi = fmaf(-S->sdots[j], S->sV[j * NP + tid], wi);
                S->sw[tid] = wi;
                if (pass == passes - 1) {
                    float s2 = wi * wi;
#pragma unroll
                    for (int o = 16; o; o >>= 1) s2 += __shfl_xor_sync(0xffffffffu, s2, o);
                    if ((tid & 31) == 0) S->sred[tid >> 5] = s2;
                }
            }
            __syncthreads();
        }

        const float b2   = S->sred[0] + S->sred[1] + S->sred[2];
        const float beta = sqrtf(fmaxf(b2, 0.f));
        if (tid == 0) S->sbeta[k] = beta;
        const float tol = 1e-6f * (fabsf(S->salpha[0]) + 1.f);
        if (beta < tol) { meff = k + 1; break; }
        if (k + 1 < m) {
            const float invb = rsqrtf(fmaxf(b2, 1e-38f));
            if (tid < 96) S->sV[(k + 1) * NP + tid] = S->sw[tid] * invb;
        }
        __syncthreads();
    }
    __syncthreads();

    // ---- lowest eigenvalue via 32-way Sturm bisection (4 rounds) ----
    if (tid < 32) {
        if (tid == 0) {
            float lo = 1e30f, hi = -1e30f;
            for (int i = 0; i < meff; ++i) {
                float r = (i > 0 ? fabsf(S->sbeta[i - 1]) : 0.f) +
                          (i < meff - 1 ? fabsf(S->sbeta[i]) : 0.f);
                lo = fminf(lo, S->salpha[i] - r);
                hi = fmaxf(hi, S->salpha[i] + r);
            }
            S->sctrl[2] = lo; S->sctrl[3] = hi;
        }
        __syncwarp();
        for (int round = 0; round < 4; ++round) {
            const float lo = S->sctrl[2], hi = S->sctrl[3];
            const float x = lo + (hi - lo) * (float)(tid + 1) * (1.f / 33.f);
            int cnt = 0;
            float dd = S->salpha[0] - x;
            if (dd < 0.f) cnt++;
            for (int i = 1; i < meff; ++i) {
                float ad = dd;
                if (fabsf(ad) < 1e-25f) ad = (ad < 0.f) ? -1e-25f : 1e-25f;
                dd = (S->salpha[i] - x) - __fdividef(S->sbeta[i - 1] * S->sbeta[i - 1], ad);
                if (dd < 0.f) cnt++;
            }
            const unsigned ball = __ballot_sync(0xffffffffu, cnt >= 1);
            if (tid == 0) {
                if (ball == 0u) {
                    S->sctrl[2] = lo + (hi - lo) * (32.f / 33.f);
                } else {
                    const int f = __ffs(ball) - 1;
                    S->sctrl[3] = lo + (hi - lo) * (float)(f + 1) * (1.f / 33.f);
                    if (f > 0) S->sctrl[2] = lo + (hi - lo) * (float)f * (1.f / 33.f);
                }
            }
            __syncwarp();
        }
        if (tid == 0) {  // inverse iteration, 2 Thomas sweeps
            const float lo = S->sctrl[2], hi = S->sctrl[3];
            const float sig = lo - 0.01f * (hi - lo) - 1e-6f;
            for (int i = 0; i < meff; ++i) S->sy[i] = 1.f;
            for (int itn = 0; itn < 2; ++itn) {
                float den = S->salpha[0] - sig;
                if (fabsf(den) < 1e-25f) den = 1e-25f;
                S->sdots[0] = (meff > 1) ? __fdividef(S->sbeta[0], den) : 0.f;
                S->sw[0] = __fdividef(S->sy[0], den);
                for (int i = 1; i < meff; ++i) {
                    float mden = (S->salpha[i] - sig) - S->sbeta[i - 1] * S->sdots[i - 1];
                    if (fabsf(mden) < 1e-25f) mden = 1e-25f;
                    S->sdots[i] = (i < meff - 1) ? __fdividef(S->sbeta[i], mden) : 0.f;
                    S->sw[i] = __fdividef(S->sy[i] - S->sbeta[i - 1] * S->sw[i - 1], mden);
                }
                S->sy[meff - 1] = S->sw[meff - 1];
                for (int i = meff - 2; i >= 0; --i) S->sy[i] = S->sw[i] - S->sdots[i] * S->sy[i + 1];
                float nn = 0.f;
                for (int i = 0; i < meff; ++i) nn += S->sy[i] * S->sy[i];
                const float inv = rsqrtf(fmaxf(nn, 1e-38f));
                for (int i = 0; i < meff; ++i) S->sy[i] *= inv;
            }
        }
    }
    __syncthreads();

    // ---- Ritz vector c2 = V^T y, normalize ----
    if (tid < 96) {
        float s = 0.f;
        for (int kk = 0; kk < meff; ++kk) s = fmaf(S->sy[kk], S->sV[kk * NP + tid], s);
        S->sc2[tid] = s;
    }
    __syncthreads();
    if (tid < 32) {
        float s = S->sc2[tid] * S->sc2[tid] + S->sc2[tid + 32] * S->sc2[tid + 32]
                + S->sc2[tid + 64] * S->sc2[tid + 64];
#pragma unroll
        for (int o = 16; o; o >>= 1) s += __shfl_xor_sync(0xffffffffu, s, o);
        if (tid == 0) S->sctrl[4] = rsqrtf(fmaxf(s, 1e-38f));
    }
    __syncthreads();
    if (tid < 96) S->sc2[tid] *= S->sctrl[4];
    __syncthreads();

    // ---- c = A * c2 (register A) ----
    opmv_reg(S->sc, Areg, S->sc2, row, jb, part);
    if (tid < 96) g_c2[tid] = S->sc2[tid];
    __syncthreads();

    // ---- packed Dpk = c_i c_j (i<=j); accumulate e2 = Fd.D on final iter ----
    const bool final_it = (iter == NITERS_EFF - 1);
    float e2 = 0.f;
    for (int t = tid; t < NPAIR; t += 384) {
        const int i = pair_row(t);
        const int j = i + (t - pair_off(i));
        const float dv = S->sc[i] * S->sc[j];
        g_Dpk[t] = dv;
        if (final_it) e2 += g_Fd[t] * dv * ((i == j) ? 1.f : 2.f);
    }

    // ---- energy on final iteration: E = 2*c^T F c - Fd.D + Enuc ----
    if (final_it) {
        float s = 0.f;
#pragma unroll
        for (int j = 0; j < 24; ++j) s = fmaf(Freg[j], S->sc[jb + j], s);
        float val = 2.f * S->sc[row] * s - e2;
#pragma unroll
        for (int o = 16; o; o >>= 1) val += __shfl_xor_sync(0xffffffffu, val, o);
        if ((tid & 31) == 0) S->sred[tid >> 5] = val;
        __syncthreads();
        if (tid == 0) {
            float e = 0.f;
#pragma unroll
            for (int w = 0; w < 12; ++w) e += S->sred[w];
            out[0] = e + gEnuc[0];
        }
    }
}

// ---------------------------------------------------------------------------
// Unified build + solve0 kernel. Blocks 0..NPAIR-1 build packed M̃; block
// NPAIR runs the (independent) iter-0 solve. Both use the dynamic smem region.
// ---------------------------------------------------------------------------
#define BSM_BYTES (96 * NP * 4)    // 37248 B > sizeof(SolveSmem) (~8.8 KB)

__global__ __launch_bounds__(384) void build_solve0(const float* __restrict__ G,
                                                    const float* __restrict__ gH,
                                                    const float* __restrict__ gA,
                                                    const float* __restrict__ gEnuc,
                                                    float* __restrict__ out) {
    extern __shared__ float dsm[];
    const int tid = threadIdx.x;

    if (blockIdx.x == NPAIR) {
        solve_body(reinterpret_cast<SolveSmem*>(dsm), gH, gA, gEnuc, out, 0, tid);
        return;
    }

    float* tC = dsm;
    const int row = blockIdx.x;            // 0..NPAIR-1, consecutive rows share p
    const int p = pair_row(row);
    const int q = p + (row - pair_off(p));

    // C[r][s] = 2G[pqrs] - G[prqs], computed during load (float4 both streams)
    const float* gAa = G + (size_t)(p * 96 + q) * 9216;
    for (int i4 = tid; i4 < 2304; i4 += 384) {   // 96*96/4
        const int r  = i4 / 24;
        const int s0 = (i4 % 24) * 4;
        float4 a = *(const float4*)(gAa + r * 96 + s0);
        float4 b = *(const float4*)(G + ((size_t)((p * 96 + r) * 96 + q)) * 96 + s0);
        float* c = tC + r * NP + s0;
        c[0] = 2.f * a.x - b.x;
        c[1] = 2.f * a.y - b.y;
        c[2] = 2.f * a.z - b.z;
        c[3] = 2.f * a.w - b.w;
    }
    __syncthreads();

    H2x4* outp = reinterpret_cast<H2x4*>(g_M) + (size_t)row * NCHUNK;
    for (int c = tid; c < NCHUNK; c += 384) {
        const int t0 = c * 8;
        int r = pair_row(t0);
        int s = r + (t0 - pair_off(r));
        __half hv[8];
#pragma unroll
        for (int u = 0; u < 8; ++u) {
            float v = tC[r * NP + s];
            if (s != r) v += tC[s * NP + r];
            hv[u] = __float2half_rn(v);
            if (++s > 95) { ++r; s = r; }
        }
        H2x4 o;
        o.h[0] = __halves2half2(hv[0], hv[1]);
        o.h[1] = __halves2half2(hv[2], hv[3]);
        o.h[2] = __halves2half2(hv[4], hv[5]);
        o.h[3] = __halves2half2(hv[6], hv[7]);
        outp[c] = o;
    }
}

// ---------------------------------------------------------------------------
// Fused: packed matvec (582 blocks) + solve in the last-finishing block.
// ---------------------------------------------------------------------------
__device__ __forceinline__ float h2x4_dot(const H2x4& m, const float* d) {
    float a = 0.f;
#pragma unroll
    for (int u = 0; u < 4; ++u) {
        float2 f = __half22float2(m.h[u]);
        a = fmaf(f.x, d[2 * u + 0], a);
        a = fmaf(f.y, d[2 * u + 1], a);
    }
    return a;
}

__global__ __launch_bounds__(384) void fused_kernel(const float* __restrict__ gH,
                                                    const float* __restrict__ gA,
                                                    const float* __restrict__ gEnuc,
                                                    float* __restrict__ out, int iter) {
    __shared__ SolveSmem S;
    __shared__ unsigned sLast;
    float* sred_mv = S.sV;               // overlay 8x12 reduce scratch

    const int tid = threadIdx.x, lane = tid & 31, wrp = tid >> 5;
    const bool has2 = (384 + tid) < NCHUNK;   // tid < 198

    float d0[8], d1[8];
    {
        const float4* Dp4 = (const float4*)g_Dpk;
        float4 a = Dp4[tid * 2], b = Dp4[tid * 2 + 1];
        d0[0] = a.x; d0[1] = a.y; d0[2] = a.z; d0[3] = a.w;
        d0[4] = b.x; d0[5] = b.y; d0[6] = b.z; d0[7] = b.w;
        if (has2) {
            float4 a2 = Dp4[(384 + tid) * 2], b2 = Dp4[(384 + tid) * 2 + 1];
            d1[0] = a2.x; d1[1] = a2.y; d1[2] = a2.z; d1[3] = a2.w;
            d1[4] = b2.x; d1[5] = b2.y; d1[6] = b2.z; d1[7] = b2.w;
        }
    }

    const int row0 = blockIdx.x * 8;
    const H2x4* base = reinterpret_cast<const H2x4*>(g_M);
#pragma unroll 1
    for (int rp = 0; rp < 4; ++rp) {
        const H2x4* p0 = base + (size_t)(row0 + 2 * rp) * NCHUNK;
        const H2x4* p1 = p0 + NCHUNK;
        H2x4 m00 = p0[tid];
        H2x4 m10 = p1[tid];
        H2x4 m01, m11;
        if (has2) { m01 = p0[384 + tid]; m11 = p1[384 + tid]; }

        float a0 = h2x4_dot(m00, d0);
        float a1 = h2x4_dot(m10, d0);
        if (has2) {
            a0 += h2x4_dot(m01, d1);
            a1 += h2x4_dot(m11, d1);
        }
#pragma unroll
        for (int o = 16; o; o >>= 1) {
            a0 += __shfl_xor_sync(0xffffffffu, a0, o);
            a1 += __shfl_xor_sync(0xffffffffu, a1, o);
        }
        if (lane == 0) { sred_mv[(2 * rp) * 12 + wrp] = a0; sred_mv[(2 * rp + 1) * 12 + wrp] = a1; }
    }
    __syncthreads();
    if (tid < 8) {
        float s = 0.f;
#pragma unroll
        for (int w = 0; w < 12; ++w) s += sred_mv[tid * 12 + w];
        g_Fd[row0 + tid] = s;
    }
    __threadfence();
    __syncthreads();
    if (tid == 0) {
        unsigned old = atomicAdd(&g_cnt, 1u);
        sLast = ((old % (unsigned)NCHUNK) == (unsigned)(NCHUNK - 1)) ? 1u : 0u;
    }
    __syncthreads();
    if (!sLast) return;

    __threadfence();   // acquire: all g_Fd writes visible
    __syncthreads();
    solve_body(&S, gH, gA, gEnuc, out, iter, tid);
}

// ---------------------------------------------------------------------------
extern "C" void kernel_launch(void* const* d_in, const int* in_sizes, int n_in,
                              void* d_out, int out_size) {
    const float* mats[3] = {nullptr, nullptr, nullptr};
    int nm = 0;
    const float* G = nullptr;
    const float* Enuc = nullptr;
    for (int i = 0; i < n_in; ++i) {
        if (in_sizes[i] == N2) { if (nm < 3) mats[nm++] = (const float*)d_in[i]; }
        else if (in_sizes[i] == N4) G = (const float*)d_in[i];
        else if (in_sizes[i] == 1) Enuc = (const float*)d_in[i];
    }
    const float* H = mats[1];
    const float* A = mats[2];
    float* out = (float*)d_out;

    cudaFuncSetAttribute(build_solve0, cudaFuncAttributeMaxDynamicSharedMemorySize, BSM_BYTES);

    build_solve0<<<NPAIR + 1, 384, BSM_BYTES>>>(G, H, A, Enuc, out);
    for (int it = 1; it < NITERS_EFF; ++it) {
        fused_kernel<<<NCHUNK, 384>>>(H, A, Enuc, out, it);
    }
}

// round 14
// speedup vs baseline: 1.0930x; 1.0930x over previous
#include <cuda_runtime.h>
#include <cuda_fp16.h>
#include <math.h>

#define NB     96
#define NP     97           // smem stride (conflict-free)
#define N2     (96*96)
#define N4     (96*96*96*96)
#define NPAIR  4656         // #(p<=q)
#define NCHUNK 582          // NPAIR/8 H2x4 chunks per row
#define MMAX   16
#define NITERS_EFF 4        // SCF steps (iters 0..3)

// persistent scratch (allowed: __device__ globals)
__device__ __half g_M[(size_t)NPAIR * NPAIR];  // 43.4 MB packed both ways
__device__ __align__(16) float g_Dpk[NPAIR];   // packed c_r*c_s (r<=s)
__device__ float  g_Fd[NPAIR];
__device__ float  g_c2[NB];
__device__ unsigned g_cnt;                     // completion counter (monotonic)
__device__ unsigned g_flag;                    // release flag for solver block

struct alignas(16) H2x4 { __half2 h[4]; };

__host__ __device__ __forceinline__ int pair_off(int p) {
    return p * 96 - (p * (p - 1)) / 2;   // index of (p,p) in packed order
}
__device__ __forceinline__ int pair_row(int t) {   // invert pair_off
    int r = (int)((193.0f - sqrtf(193.0f * 193.0f - 8.0f * (float)t)) * 0.5f);
    while (pair_off(r + 1) <= t) ++r;
    while (pair_off(r) > t) --r;
    return r;
}

// ---------------------------------------------------------------------------
// Register-operator matvec (R11 version): dst = Reg-matrix * src (src in smem).
// thread = (row = tid>>2, part = tid&3); Reg holds Mat[row][part*24 .. +24].
// ---------------------------------------------------------------------------
__device__ __forceinline__ void opmv_reg(float* __restrict__ dst,
                                         const float (&Reg)[24],
                                         const float* __restrict__ src,
                                         int row, int jb, int part) {
    float s = 0.f;
#pragma unroll
    for (int j = 0; j < 24; ++j) s = fmaf(Reg[j], src[jb + j], s);
    s += __shfl_xor_sync(0xffffffffu, s, 1);
    s += __shfl_xor_sync(0xffffffffu, s, 2);
    if (part == 0) dst[row] = s;
}

// ---------------------------------------------------------------------------
// Shared-memory block for the solve (~8.7 KB)
// ---------------------------------------------------------------------------
struct SolveSmem {
    float sV[MMAX * NP];
    float sw[96], st1[96], st2[96];
    float sdots[96];
    float salpha[MMAX], sbeta[MMAX], sy[MMAX];
    float sc2[96], sc[96];
    float sctrl[16], sred[16];
};

// Initialize + normalize the Lanczos start vector in S->sV row 0.
__device__ void solve_prep(SolveSmem* S, int iter, int tid) {
    if (tid < 96) {
        float v;
        if (iter == 0) {
            unsigned h = (unsigned)tid * 2654435761u + 12345u;
            h ^= h >> 13; h *= 0x85ebca6bu; h ^= h >> 16;
            v = (float)(h & 0xFFFFu) * (1.f / 65536.f) - 0.5f;
        } else {
            v = g_c2[tid];
        }
        S->sV[tid] = v;
    }
    __syncthreads();
    if (tid < 32) {
        float s = S->sV[tid] * S->sV[tid] + S->sV[tid + 32] * S->sV[tid + 32]
                + S->sV[tid + 64] * S->sV[tid + 64];
#pragma unroll
        for (int o = 16; o; o >>= 1) s += __shfl_xor_sync(0xffffffffu, s, o);
        if (tid == 0) S->sctrl[0] = rsqrtf(fmaxf(s, 1e-30f));
    }
    __syncthreads();
    if (tid < 96) S->sV[tid] *= S->sctrl[0];
    __syncthreads();
}

// Lanczos loop -> eigvec -> D update -> (final) energy. sV row 0 must be ready.
__device__ void solve_tail(SolveSmem* S,
                           const float (&Areg)[24], const float (&Freg)[24],
                           const float* __restrict__ gEnuc,
                           float* __restrict__ out, int iter, int tid) {
    const int row = tid >> 2, part = tid & 3, jb = part * 24;
    const int m      = (iter == 0) ? 16 : ((iter == NITERS_EFF - 1) ? 9 : 6);
    const int passes = (iter == 0) ? 2 : 1;

    int meff = m;
    for (int k = 0; k < m; ++k) {
        opmv_reg(S->st1, Areg, S->sV + k * NP, row, jb, part);
        __syncthreads();
        opmv_reg(S->st2, Freg, S->st1, row, jb, part);
        __syncthreads();
        opmv_reg(S->sw, Areg, S->st2, row, jb, part);
        __syncthreads();

#pragma unroll 1
        for (int pass = 0; pass < passes; ++pass) {
            {
                const int j = tid >> 2;
                float s = 0.f;
                if (j <= k) {
#pragma unroll
                    for (int i = 0; i < 24; ++i)
                        s = fmaf(S->sV[j * NP + jb + i], S->sw[jb + i], s);
                }
                s += __shfl_xor_sync(0xffffffffu, s, 1);
                s += __shfl_xor_sync(0xffffffffu, s, 2);
                if (part == 0 && j <= k) S->sdots[j] = s;
            }
            __syncthreads();
            if (pass == 0 && tid == 0) S->salpha[k] = S->sdots[k];
            if (tid < 96) {
                float wi = S->sw[tid];
                for (int j = 0; j <= k; ++j) wi = fmaf(-S->sdots[j], S->sV[j * NP + tid], wi);
                S->sw[tid] = wi;
                if (pass == passes - 1) {
                    float s2 = wi * wi;
#pragma unroll
                    for (int o = 16; o; o >>= 1) s2 += __shfl_xor_sync(0xffffffffu, s2, o);
                    if ((tid & 31) == 0) S->sred[tid >> 5] = s2;
                }
            }
            __syncthreads();
        }

        const float b2   = S->sred[0] + S->sred[1] + S->sred[2];
        const float beta = sqrtf(fmaxf(b2, 0.f));
        if (tid == 0) S->sbeta[k] = beta;
        const float tol = 1e-6f * (fabsf(S->salpha[0]) + 1.f);
        if (beta < tol) { meff = k + 1; break; }
        if (k + 1 < m) {
            const float invb = rsqrtf(fmaxf(b2, 1e-38f));
            if (tid < 96) S->sV[(k + 1) * NP + tid] = S->sw[tid] * invb;
        }
        __syncthreads();
    }
    __syncthreads();

    // ---- lowest eigenvalue via 32-way Sturm bisection (4 rounds) ----
    if (tid < 32) {
        if (tid == 0) {
            float lo = 1e30f, hi = -1e30f;
            for (int i = 0; i < meff; ++i) {
                float r = (i > 0 ? fabsf(S->sbeta[i - 1]) : 0.f) +
                          (i < meff - 1 ? fabsf(S->sbeta[i]) : 0.f);
                lo = fminf(lo, S->salpha[i] - r);
                hi = fmaxf(hi, S->salpha[i] + r);
            }
            S->sctrl[2] = lo; S->sctrl[3] = hi;
        }
        __syncwarp();
        for (int round = 0; round < 4; ++round) {
            const float lo = S->sctrl[2], hi = S->sctrl[3];
            const float x = lo + (hi - lo) * (float)(tid + 1) * (1.f / 33.f);
            int cnt = 0;
            float dd = S->salpha[0] - x;
            if (dd < 0.f) cnt++;
            for (int i = 1; i < meff; ++i) {
                float ad = dd;
                if (fabsf(ad) < 1e-25f) ad = (ad < 0.f) ? -1e-25f : 1e-25f;
                dd = (S->salpha[i] - x) - __fdividef(S->sbeta[i - 1] * S->sbeta[i - 1], ad);
                if (dd < 0.f) cnt++;
            }
            const unsigned ball = __ballot_sync(0xffffffffu, cnt >= 1);
            if (tid == 0) {
                if (ball == 0u) {
                    S->sctrl[2] = lo + (hi - lo) * (32.f / 33.f);
                } else {
                    const int f = __ffs(ball) - 1;
                    S->sctrl[3] = lo + (hi - lo) * (float)(f + 1) * (1.f / 33.f);
                    if (f > 0) S->sctrl[2] = lo + (hi - lo) * (float)f * (1.f / 33.f);
                }
            }
            __syncwarp();
        }
        if (tid == 0) {  // inverse iteration, 2 Thomas sweeps
            const float lo = S->sctrl[2], hi = S->sctrl[3];
            const float sig = lo - 0.01f * (hi - lo) - 1e-6f;
            for (int i = 0; i < meff; ++i) S->sy[i] = 1.f;
            for (int itn = 0; itn < 2; ++itn) {
                float den = S->salpha[0] - sig;
                if (fabsf(den) < 1e-25f) den = 1e-25f;
                S->sdots[0] = (meff > 1) ? __fdividef(S->sbeta[0], den) : 0.f;
                S->sw[0] = __fdividef(S->sy[0], den);
                for (int i = 1; i < meff; ++i) {
                    float mden = (S->salpha[i] - sig) - S->sbeta[i - 1] * S->sdots[i - 1];
                    if (fabsf(mden) < 1e-25f) mden = 1e-25f;
                    S->sdots[i] = (i < meff - 1) ? __fdividef(S->sbeta[i], mden) : 0.f;
                    S->sw[i] = __fdividef(S->sy[i] - S->sbeta[i - 1] * S->sw[i - 1], mden);
                }
                S->sy[meff - 1] = S->sw[meff - 1];
                for (int i = meff - 2; i >= 0; --i) S->sy[i] = S->sw[i] - S->sdots[i] * S->sy[i + 1];
                float nn = 0.f;
                for (int i = 0; i < meff; ++i) nn += S->sy[i] * S->sy[i];
                const float inv = rsqrtf(fmaxf(nn, 1e-38f));
                for (int i = 0; i < meff; ++i) S->sy[i] *= inv;
            }
        }
    }
    __syncthreads();

    // ---- Ritz vector c2 = V^T y, normalize ----
    if (tid < 96) {
        float s = 0.f;
        for (int kk = 0; kk < meff; ++kk) s = fmaf(S->sy[kk], S->sV[kk * NP + tid], s);
        S->sc2[tid] = s;
    }
    __syncthreads();
    if (tid < 32) {
        float s = S->sc2[tid] * S->sc2[tid] + S->sc2[tid + 32] * S->sc2[tid + 32]
                + S->sc2[tid + 64] * S->sc2[tid + 64];
#pragma unroll
        for (int o = 16; o; o >>= 1) s += __shfl_xor_sync(0xffffffffu, s, o);
        if (tid == 0) S->sctrl[4] = rsqrtf(fmaxf(s, 1e-38f));
    }
    __syncthreads();
    if (tid < 96) S->sc2[tid] *= S->sctrl[4];
    __syncthreads();

    // ---- c = A * c2 (register A) ----
    opmv_reg(S->sc, Areg, S->sc2, row, jb, part);
    if (tid < 96) g_c2[tid] = S->sc2[tid];
    __syncthreads();

    // ---- packed Dpk = c_i c_j (i<=j); accumulate e2 = Fd.D on final iter ----
    const bool final_it = (iter == NITERS_EFF - 1);
    float e2 = 0.f;
    for (int t = tid; t < NPAIR; t += 384) {
        const int i = pair_row(t);
        const int j = i + (t - pair_off(i));
        const float dv = S->sc[i] * S->sc[j];
        g_Dpk[t] = dv;
        if (final_it) e2 += g_Fd[t] * dv * ((i == j) ? 1.f : 2.f);
    }

    // ---- energy on final iteration: E = 2*c^T F c - Fd.D + Enuc ----
    if (final_it) {
        float s = 0.f;
#pragma unroll
        for (int j = 0; j < 24; ++j) s = fmaf(Freg[j], S->sc[jb + j], s);
        float val = 2.f * S->sc[row] * s - e2;
#pragma unroll
        for (int o = 16; o; o >>= 1) val += __shfl_xor_sync(0xffffffffu, val, o);
        if ((tid & 31) == 0) S->sred[tid >> 5] = val;
        __syncthreads();
        if (tid == 0) {
            float e = 0.f;
#pragma unroll
            for (int w = 0; w < 12; ++w) e += S->sred[w];
            out[0] = e + gEnuc[0];
        }
    }
}

// ---------------------------------------------------------------------------
// Build packed M̃ (standalone, 256 threads — keeps its own low reg count):
//   C[r][s] = 2G[pqrs] - G[prqs]; M̃[row][(r,s)] = C[r][s] + (r<s ? C[s][r] : 0)
// ---------------------------------------------------------------------------
#define BSM_BYTES (96 * NP * 4)
__global__ __launch_bounds__(256) void build_M(const float* __restrict__ G) {
    extern __shared__ float tC[];

    const int row = blockIdx.x;            // 0..NPAIR-1, consecutive rows share p
    const int p = pair_row(row);
    const int q = p + (row - pair_off(p));

    const float* gAa = G + (size_t)(p * 96 + q) * 9216;
    for (int i4 = threadIdx.x; i4 < 2304; i4 += 256) {   // 96*96/4
        const int r  = i4 / 24;
        const int s0 = (i4 % 24) * 4;
        float4 a = *(const float4*)(gAa + r * 96 + s0);
        float4 b = *(const float4*)(G + ((size_t)((p * 96 + r) * 96 + q)) * 96 + s0);
        float* c = tC + r * NP + s0;
        c[0] = 2.f * a.x - b.x;
        c[1] = 2.f * a.y - b.y;
        c[2] = 2.f * a.z - b.z;
        c[3] = 2.f * a.w - b.w;
    }
    __syncthreads();

    H2x4* outp = reinterpret_cast<H2x4*>(g_M) + (size_t)row * NCHUNK;
    for (int c = threadIdx.x; c < NCHUNK; c += 256) {
        const int t0 = c * 8;
        int r = pair_row(t0);
        int s = r + (t0 - pair_off(r));
        __half hv[8];
#pragma unroll
        for (int u = 0; u < 8; ++u) {
            float v = tC[r * NP + s];
            if (s != r) v += tC[s * NP + r];
            hv[u] = __float2half_rn(v);
            if (++s > 95) { ++r; s = r; }
        }
        H2x4 o;
        o.h[0] = __halves2half2(hv[0], hv[1]);
        o.h[1] = __halves2half2(hv[2], hv[3]);
        o.h[2] = __halves2half2(hv[4], hv[5]);
        o.h[3] = __halves2half2(hv[6], hv[7]);
        outp[c] = o;
    }
}

// ---------------------------------------------------------------------------
// Standalone solve (iteration 0: F = H only)
// ---------------------------------------------------------------------------
__global__ __launch_bounds__(384) void solve_kernel(const float* __restrict__ gH,
                                                    const float* __restrict__ gA,
                                                    const float* __restrict__ gEnuc,
                                                    float* __restrict__ out) {
    __shared__ SolveSmem S;
    const int tid = threadIdx.x;
    const int row = tid >> 2, part = tid & 3, jb = part * 24;

    float Areg[24], Freg[24];
    const float* ga = gA + row * 96 + jb;
    const float* gh = gH + row * 96 + jb;
#pragma unroll
    for (int j = 0; j < 24; ++j) { Areg[j] = ga[j]; Freg[j] = gh[j]; }

    solve_prep(&S, 0, tid);
    solve_tail(&S, Areg, Freg, gEnuc, out, 0, tid);
}

// ---------------------------------------------------------------------------
// Fused: 582 matvec blocks + 1 DEDICATED solver block (blockIdx == NCHUNK).
// Solver preloads A/H and inits the start vector while matvec blocks stream M,
// spins on g_flag (set by the last-finishing matvec block), then gathers Fd.
// ---------------------------------------------------------------------------
__device__ __forceinline__ float h2x4_dot(const H2x4& m, const float* d) {
    float a = 0.f;
#pragma unroll
    for (int u = 0; u < 4; ++u) {
        float2 f = __half22float2(m.h[u]);
        a = fmaf(f.x, d[2 * u + 0], a);
        a = fmaf(f.y, d[2 * u + 1], a);
    }
    return a;
}

__global__ __launch_bounds__(384) void fused_kernel(const float* __restrict__ gH,
                                                    const float* __restrict__ gA,
                                                    const float* __restrict__ gEnuc,
                                                    float* __restrict__ out, int iter) {
    __shared__ SolveSmem S;
    const int tid = threadIdx.x;

    if (blockIdx.x == NCHUNK) {
        // ---- dedicated solver block ----
        const int row = tid >> 2, part = tid & 3, jb = part * 24;
        float Areg[24], Freg[24];
        const float* ga = gA + row * 96 + jb;
        const float* gh = gH + row * 96 + jb;
#pragma unroll
        for (int j = 0; j < 24; ++j) { Areg[j] = ga[j]; Freg[j] = gh[j]; }

        solve_prep(&S, iter, tid);   // warm-start vector (g_c2 from prev iter)

        if (tid == 0) {
            while (atomicAdd(&g_flag, 0u) == 0u) { __nanosleep(128); }
            atomicExch(&g_flag, 0u);   // reset for next launch (stream-ordered)
        }
        __syncthreads();
        __threadfence();               // acquire: all g_Fd writes visible

#pragma unroll
        for (int j = 0; j < 24; ++j) {
            const int col = jb + j;
            const int a = row < col ? row : col, b = row < col ? col : row;
            Freg[j] += g_Fd[pair_off(a) + (b - a)];
        }
        solve_tail(&S, Areg, Freg, gEnuc, out, iter, tid);
        return;
    }

    // ---- matvec blocks ----
    float* sred_mv = S.sV;               // overlay 8x12 reduce scratch
    const int lane = tid & 31, wrp = tid >> 5;
    const bool has2 = (384 + tid) < NCHUNK;   // tid < 198

    float d0[8], d1[8];
    {
        const float4* Dp4 = (const float4*)g_Dpk;
        float4 a = Dp4[tid * 2], b = Dp4[tid * 2 + 1];
        d0[0] = a.x; d0[1] = a.y; d0[2] = a.z; d0[3] = a.w;
        d0[4] = b.x; d0[5] = b.y; d0[6] = b.z; d0[7] = b.w;
        if (has2) {
            float4 a2 = Dp4[(384 + tid) * 2], b2 = Dp4[(384 + tid) * 2 + 1];
            d1[0] = a2.x; d1[1] = a2.y; d1[2] = a2.z; d1[3] = a2.w;
            d1[4] = b2.x; d1[5] = b2.y; d1[6] = b2.z; d1[7] = b2.w;
        }
    }

    const int row0 = blockIdx.x * 8;
    const H2x4* base = reinterpret_cast<const H2x4*>(g_M);
#pragma unroll 1
    for (int rp = 0; rp < 4; ++rp) {
        const H2x4* p0 = base + (size_t)(row0 + 2 * rp) * NCHUNK;
        const H2x4* p1 = p0 + NCHUNK;
        H2x4 m00 = p0[tid];
        H2x4 m10 = p1[tid];
        H2x4 m01, m11;
        if (has2) { m01 = p0[384 + tid]; m11 = p1[384 + tid]; }

        float a0 = h2x4_dot(m00, d0);
        float a1 = h2x4_dot(m10, d0);
        if (has2) {
            a0 += h2x4_dot(m01, d1);
            a1 += h2x4_dot(m11, d1);
        }
#pragma unroll
        for (int o = 16; o; o >>= 1) {
            a0 += __shfl_xor_sync(0xffffffffu, a0, o);
            a1 += __shfl_xor_sync(0xffffffffu, a1, o);
        }
        if (lane == 0) { sred_mv[(2 * rp) * 12 + wrp] = a0; sred_mv[(2 * rp + 1) * 12 + wrp] = a1; }
    }
    __syncthreads();
    if (tid < 8) {
        float s = 0.f;
#pragma unroll
        for (int w = 0; w < 12; ++w) s += sred_mv[tid * 12 + w];
        g_Fd[row0 + tid] = s;
    }
    __threadfence();
    __syncthreads();
    if (tid == 0) {
        unsigned old = atomicAdd(&g_cnt, 1u);
        if ((old % (unsigned)NCHUNK) == (unsigned)(NCHUNK - 1))
            atomicExch(&g_flag, 1u);   // release to solver block
    }
}

// ---------------------------------------------------------------------------
extern "C" void kernel_launch(void* const* d_in, const int* in_sizes, int n_in,
                              void* d_out, int out_size) {
    const float* mats[3] = {nullptr, nullptr, nullptr};
    int nm = 0;
    const float* G = nullptr;
    const float* Enuc = nullptr;
    for (int i = 0; i < n_in; ++i) {
        if (in_sizes[i] == N2) { if (nm < 3) mats[nm++] = (const float*)d_in[i]; }
        else if (in_sizes[i] == N4) G = (const float*)d_in[i];
        else if (in_sizes[i] == 1) Enuc = (const float*)d_in[i];
    }
    const float* H = mats[1];
    const float* A = mats[2];
    float* out = (float*)d_out;

    cudaFuncSetAttribute(build_M, cudaFuncAttributeMaxDynamicSharedMemorySize, BSM_BYTES);

    build_M<<<NPAIR, 256, BSM_BYTES>>>(G);
    solve_kernel<<<1, 384>>>(H, A, Enuc, out);
    for (int it = 1; it < NITERS_EFF; ++it) {
        fused_kernel<<<NCHUNK + 1, 384>>>(H, A, Enuc, out, it);
    }
}

// round 15
// speedup vs baseline: 1.1960x; 1.0942x over previous
#include <cuda_runtime.h>
#include <cuda_fp16.h>
#include <math.h>

#define NB     96
#define NP     97           // smem stride (conflict-free)
#define N2     (96*96)
#define N4     (96*96*96*96)
#define NPAIR  4656         // #(p<=q)
#define NCHUNK 582          // NPAIR/8 H2x4 chunks per row
#define MMAX   12
#define NITERS_EFF 4        // SCF steps (iters 0..3)

// persistent scratch (allowed: __device__ globals)
__device__ __half g_M[(size_t)NPAIR * NPAIR];  // 43.4 MB packed both ways
__device__ __align__(16) float g_Dpk[NPAIR];   // packed c_r*c_s (r<=s)
__device__ float  g_Fd[NPAIR];
__device__ float  g_c2[NB];
__device__ unsigned g_cnt;                     // completion counter (monotonic)
__device__ unsigned g_flag;                    // release flag for solver block

struct alignas(16) H2x4 { __half2 h[4]; };

__host__ __device__ __forceinline__ int pair_off(int p) {
    return p * 96 - (p * (p - 1)) / 2;   // index of (p,p) in packed order
}
__device__ __forceinline__ int pair_row(int t) {   // invert pair_off
    int r = (int)((193.0f - sqrtf(193.0f * 193.0f - 8.0f * (float)t)) * 0.5f);
    while (pair_off(r + 1) <= t) ++r;
    while (pair_off(r) > t) --r;
    return r;
}

// ---------------------------------------------------------------------------
// Register-operator matvec: dst = Reg-matrix * src (src in smem).
// thread = (row = tid>>2, part = tid&3); Reg holds Mat[row][part*24 .. +24].
// ---------------------------------------------------------------------------
__device__ __forceinline__ void opmv_reg(float* __restrict__ dst,
                                         const float (&Reg)[24],
                                         const float* __restrict__ src,
                                         int row, int jb, int part) {
    float s = 0.f;
#pragma unroll
    for (int j = 0; j < 24; ++j) s = fmaf(Reg[j], src[jb + j], s);
    s += __shfl_xor_sync(0xffffffffu, s, 1);
    s += __shfl_xor_sync(0xffffffffu, s, 2);
    if (part == 0) dst[row] = s;
}

// ---------------------------------------------------------------------------
// Shared-memory block for the solve (~7 KB)
// ---------------------------------------------------------------------------
struct SolveSmem {
    float sV[MMAX * NP];
    float sw[96], st1[96], st2[96];
    float sdots[96];
    float salpha[MMAX], sbeta[MMAX], sy[MMAX];
    float sc2[96], sc[96];
    float sctrl[16], sred[16];
};

// Initialize + normalize the Lanczos start vector in S->sV row 0.
__device__ void solve_prep(SolveSmem* S, int iter, int tid) {
    if (tid < 96) {
        float v;
        if (iter == 0) {
            unsigned h = (unsigned)tid * 2654435761u + 12345u;
            h ^= h >> 13; h *= 0x85ebca6bu; h ^= h >> 16;
            v = (float)(h & 0xFFFFu) * (1.f / 65536.f) - 0.5f;
        } else {
            v = g_c2[tid];
        }
        S->sV[tid] = v;
    }
    __syncthreads();
    if (tid < 32) {
        float s = S->sV[tid] * S->sV[tid] + S->sV[tid + 32] * S->sV[tid + 32]
                + S->sV[tid + 64] * S->sV[tid + 64];
#pragma unroll
        for (int o = 16; o; o >>= 1) s += __shfl_xor_sync(0xffffffffu, s, o);
        if (tid == 0) S->sctrl[0] = rsqrtf(fmaxf(s, 1e-30f));
    }
    __syncthreads();
    if (tid < 96) S->sV[tid] *= S->sctrl[0];
    __syncthreads();
}

// Lanczos loop -> eigvec -> D update -> (final) energy. sV row 0 must be ready.
__device__ void solve_tail(SolveSmem* S,
                           const float (&Areg)[24], const float (&Freg)[24],
                           const float* __restrict__ gEnuc,
                           float* __restrict__ out, int iter, int tid) {
    const int row = tid >> 2, part = tid & 3, jb = part * 24;
    const int m      = (iter == 0) ? 12 : ((iter == NITERS_EFF - 1) ? 8 : 4);
    const int passes = (iter == 0) ? 2 : 1;

    int meff = m;
    for (int k = 0; k < m; ++k) {
        opmv_reg(S->st1, Areg, S->sV + k * NP, row, jb, part);
        __syncthreads();
        opmv_reg(S->st2, Freg, S->st1, row, jb, part);
        __syncthreads();
        opmv_reg(S->sw, Areg, S->st2, row, jb, part);
        __syncthreads();

#pragma unroll 1
        for (int pass = 0; pass < passes; ++pass) {
            {
                const int j = tid >> 2;
                float s = 0.f;
                if (j <= k) {
#pragma unroll
                    for (int i = 0; i < 24; ++i)
                        s = fmaf(S->sV[j * NP + jb + i], S->sw[jb + i], s);
                }
                s += __shfl_xor_sync(0xffffffffu, s, 1);
                s += __shfl_xor_sync(0xffffffffu, s, 2);
                if (part == 0 && j <= k) S->sdots[j] = s;
            }
            __syncthreads();
            if (pass == 0 && tid == 0) S->salpha[k] = S->sdots[k];
            if (tid < 96) {
                float wi = S->sw[tid];
                for (int j = 0; j <= k; ++j) wi = fmaf(-S->sdots[j], S->sV[j * NP + tid], wi);
                S->sw[tid] = wi;
                if (pass == passes - 1) {
                    float s2 = wi * wi;
#pragma unroll
                    for (int o = 16; o; o >>= 1) s2 += __shfl_xor_sync(0xffffffffu, s2, o);
                    if ((tid & 31) == 0) S->sred[tid >> 5] = s2;
                }
            }
            __syncthreads();
        }

        const float b2   = S->sred[0] + S->sred[1] + S->sred[2];
        const float beta = sqrtf(fmaxf(b2, 0.f));
        if (tid == 0) S->sbeta[k] = beta;
        const float tol = 1e-6f * (fabsf(S->salpha[0]) + 1.f);
        if (beta < tol) { meff = k + 1; break; }
        if (k + 1 < m) {
            const float invb = rsqrtf(fmaxf(b2, 1e-38f));
            if (tid < 96) S->sV[(k + 1) * NP + tid] = S->sw[tid] * invb;
        }
        __syncthreads();
    }
    __syncthreads();

    // ---- lowest eigenvalue via 32-way Sturm bisection (4 rounds) ----
    if (tid < 32) {
        if (tid == 0) {
            float lo = 1e30f, hi = -1e30f;
            for (int i = 0; i < meff; ++i) {
                float r = (i > 0 ? fabsf(S->sbeta[i - 1]) : 0.f) +
                          (i < meff - 1 ? fabsf(S->sbeta[i]) : 0.f);
                lo = fminf(lo, S->salpha[i] - r);
                hi = fmaxf(hi, S->salpha[i] + r);
            }
            S->sctrl[2] = lo; S->sctrl[3] = hi;
        }
        __syncwarp();
        for (int round = 0; round < 4; ++round) {
            const float lo = S->sctrl[2], hi = S->sctrl[3];
            const float x = lo + (hi - lo) * (float)(tid + 1) * (1.f / 33.f);
            int cnt = 0;
            float dd = S->salpha[0] - x;
            if (dd < 0.f) cnt++;
            for (int i = 1; i < meff; ++i) {
                float ad = dd;
                if (fabsf(ad) < 1e-25f) ad = (ad < 0.f) ? -1e-25f : 1e-25f;
                dd = (S->salpha[i] - x) - __fdividef(S->sbeta[i - 1] * S->sbeta[i - 1], ad);
                if (dd < 0.f) cnt++;
            }
            const unsigned ball = __ballot_sync(0xffffffffu, cnt >= 1);
            if (tid == 0) {
                if (ball == 0u) {
                    S->sctrl[2] = lo + (hi - lo) * (32.f / 33.f);
                } else {
                    const int f = __ffs(ball) - 1;
                    S->sctrl[3] = lo + (hi - lo) * (float)(f + 1) * (1.f / 33.f);
                    if (f > 0) S->sctrl[2] = lo + (hi - lo) * (float)f * (1.f / 33.f);
                }
            }
            __syncwarp();
        }
        if (tid == 0) {  // inverse iteration, 2 Thomas sweeps
            const float lo = S->sctrl[2], hi = S->sctrl[3];
            const float sig = lo - 0.01f * (hi - lo) - 1e-6f;
            for (int i = 0; i < meff; ++i) S->sy[i] = 1.f;
            for (int itn = 0; itn < 2; ++itn) {
                float den = S->salpha[0] - sig;
                if (fabsf(den) < 1e-25f) den = 1e-25f;
                S->sdots[0] = (meff > 1) ? __fdividef(S->sbeta[0], den) : 0.f;
                S->sw[0] = __fdividef(S->sy[0], den);
                for (int i = 1; i < meff; ++i) {
                    float mden = (S->salpha[i] - sig) - S->sbeta[i - 1] * S->sdots[i - 1];
                    if (fabsf(mden) < 1e-25f) mden = 1e-25f;
                    S->sdots[i] = (i < meff - 1) ? __fdividef(S->sbeta[i], mden) : 0.f;
                    S->sw[i] = __fdividef(S->sy[i] - S->sbeta[i - 1] * S->sw[i - 1], mden);
                }
                S->sy[meff - 1] = S->sw[meff - 1];
                for (int i = meff - 2; i >= 0; --i) S->sy[i] = S->sw[i] - S->sdots[i] * S->sy[i + 1];
                float nn = 0.f;
                for (int i = 0; i < meff; ++i) nn += S->sy[i] * S->sy[i];
                const float inv = rsqrtf(fmaxf(nn, 1e-38f));
                for (int i = 0; i < meff; ++i) S->sy[i] *= inv;
            }
        }
    }
    __syncthreads();

    // ---- Ritz vector c2 = V^T y, normalize ----
    if (tid < 96) {
        float s = 0.f;
        for (int kk = 0; kk < meff; ++kk) s = fmaf(S->sy[kk], S->sV[kk * NP + tid], s);
        S->sc2[tid] = s;
    }
    __syncthreads();
    if (tid < 32) {
        float s = S->sc2[tid] * S->sc2[tid] + S->sc2[tid + 32] * S->sc2[tid + 32]
                + S->sc2[tid + 64] * S->sc2[tid + 64];
#pragma unroll
        for (int o = 16; o; o >>= 1) s += __shfl_xor_sync(0xffffffffu, s, o);
        if (tid == 0) S->sctrl[4] = rsqrtf(fmaxf(s, 1e-38f));
    }
    __syncthreads();
    if (tid < 96) S->sc2[tid] *= S->sctrl[4];
    __syncthreads();

    // ---- c = A * c2 (register A) ----
    opmv_reg(S->sc, Areg, S->sc2, row, jb, part);
    if (tid < 96) g_c2[tid] = S->sc2[tid];
    __syncthreads();

    // ---- packed Dpk = c_i c_j (i<=j) — only if a next matvec consumes it;
    //      on the final iteration just accumulate e2 = Fd.D ----
    const bool final_it = (iter == NITERS_EFF - 1);
    float e2 = 0.f;
    for (int t = tid; t < NPAIR; t += 384) {
        const int i = pair_row(t);
        const int j = i + (t - pair_off(i));
        const float dv = S->sc[i] * S->sc[j];
        if (!final_it) g_Dpk[t] = dv;
        else           e2 += g_Fd[t] * dv * ((i == j) ? 1.f : 2.f);
    }

    // ---- energy on final iteration: E = 2*c^T F c - Fd.D + Enuc ----
    if (final_it) {
        float s = 0.f;
#pragma unroll
        for (int j = 0; j < 24; ++j) s = fmaf(Freg[j], S->sc[jb + j], s);
        float val = 2.f * S->sc[row] * s - e2;
#pragma unroll
        for (int o = 16; o; o >>= 1) val += __shfl_xor_sync(0xffffffffu, val, o);
        if ((tid & 31) == 0) S->sred[tid >> 5] = val;
        __syncthreads();
        if (tid == 0) {
            float e = 0.f;
#pragma unroll
            for (int w = 0; w < 12; ++w) e += S->sred[w];
            out[0] = e + gEnuc[0];
        }
    }
}

// ---------------------------------------------------------------------------
// Build packed M̃ (standalone, 256 threads — keeps its own low reg count):
//   C[r][s] = 2G[pqrs] - G[prqs]; M̃[row][(r,s)] = C[r][s] + (r<s ? C[s][r] : 0)
// ---------------------------------------------------------------------------
#define BSM_BYTES (96 * NP * 4)
__global__ __launch_bounds__(256) void build_M(const float* __restrict__ G) {
    extern __shared__ float tC[];

    const int row = blockIdx.x;            // 0..NPAIR-1, consecutive rows share p
    const int p = pair_row(row);
    const int q = p + (row - pair_off(p));

    const float* gAa = G + (size_t)(p * 96 + q) * 9216;
    for (int i4 = threadIdx.x; i4 < 2304; i4 += 256) {   // 96*96/4
        const int r  = i4 / 24;
        const int s0 = (i4 % 24) * 4;
        float4 a = *(const float4*)(gAa + r * 96 + s0);
        float4 b = *(const float4*)(G + ((size_t)((p * 96 + r) * 96 + q)) * 96 + s0);
        float* c = tC + r * NP + s0;
        c[0] = 2.f * a.x - b.x;
        c[1] = 2.f * a.y - b.y;
        c[2] = 2.f * a.z - b.z;
        c[3] = 2.f * a.w - b.w;
    }
    __syncthreads();

    H2x4* outp = reinterpret_cast<H2x4*>(g_M) + (size_t)row * NCHUNK;
    for (int c = threadIdx.x; c < NCHUNK; c += 256) {
        const int t0 = c * 8;
        int r = pair_row(t0);
        int s = r + (t0 - pair_off(r));
        __half hv[8];
#pragma unroll
        for (int u = 0; u < 8; ++u) {
            float v = tC[r * NP + s];
            if (s != r) v += tC[s * NP + r];
            hv[u] = __float2half_rn(v);
            if (++s > 95) { ++r; s = r; }
        }
        H2x4 o;
        o.h[0] = __halves2half2(hv[0], hv[1]);
        o.h[1] = __halves2half2(hv[2], hv[3]);
        o.h[2] = __halves2half2(hv[4], hv[5]);
        o.h[3] = __halves2half2(hv[6], hv[7]);
        outp[c] = o;
    }
}

// ---------------------------------------------------------------------------
// Standalone solve (iteration 0: F = H only)
// ---------------------------------------------------------------------------
__global__ __launch_bounds__(384) void solve_kernel(const float* __restrict__ gH,
                                                    const float* __restrict__ gA,
                                                    const float* __restrict__ gEnuc,
                                                    float* __restrict__ out) {
    __shared__ SolveSmem S;
    const int tid = threadIdx.x;
    const int row = tid >> 2, part = tid & 3, jb = part * 24;

    float Areg[24], Freg[24];
    const float* ga = gA + row * 96 + jb;
    const float* gh = gH + row * 96 + jb;
#pragma unroll
    for (int j = 0; j < 24; ++j) { Areg[j] = ga[j]; Freg[j] = gh[j]; }

    solve_prep(&S, 0, tid);
    solve_tail(&S, Areg, Freg, gEnuc, out, 0, tid);
}

// ---------------------------------------------------------------------------
// Fused: 582 matvec blocks + 1 DEDICATED solver block (blockIdx == NCHUNK).
// Solver preloads A/H and inits the start vector while matvec blocks stream M,
// spins on g_flag (set by the last-finishing matvec block), then gathers Fd.
// ---------------------------------------------------------------------------
__device__ __forceinline__ float h2x4_dot(const H2x4& m, const float* d) {
    float a = 0.f;
#pragma unroll
    for (int u = 0; u < 4; ++u) {
        float2 f = __half22float2(m.h[u]);
        a = fmaf(f.x, d[2 * u + 0], a);
        a = fmaf(f.y, d[2 * u + 1], a);
    }
    return a;
}

__global__ __launch_bounds__(384) void fused_kernel(const float* __restrict__ gH,
                                                    const float* __restrict__ gA,
                                                    const float* __restrict__ gEnuc,
                                                    float* __restrict__ out, int iter) {
    __shared__ SolveSmem S;
    const int tid = threadIdx.x;

    if (blockIdx.x == NCHUNK) {
        // ---- dedicated solver block ----
        const int row = tid >> 2, part = tid & 3, jb = part * 24;
        float Areg[24], Freg[24];
        const float* ga = gA + row * 96 + jb;
        const float* gh = gH + row * 96 + jb;
#pragma unroll
        for (int j = 0; j < 24; ++j) { Areg[j] = ga[j]; Freg[j] = gh[j]; }

        solve_prep(&S, iter, tid);   // warm-start vector (g_c2 from prev iter)

        if (tid == 0) {
            while (atomicAdd(&g_flag, 0u) == 0u) { __nanosleep(128); }
            atomicExch(&g_flag, 0u);   // reset for next launch (stream-ordered)
        }
        __syncthreads();
        __threadfence();               // acquire: all g_Fd writes visible

#pragma unroll
        for (int j = 0; j < 24; ++j) {
            const int col = jb + j;
            const int a = row < col ? row : col, b = row < col ? col : row;
            Freg[j] += g_Fd[pair_off(a) + (b - a)];
        }
        solve_tail(&S, Areg, Freg, gEnuc, out, iter, tid);
        return;
    }

    // ---- matvec blocks ----
    float* sred_mv = S.sV;               // overlay 8x12 reduce scratch
    const int lane = tid & 31, wrp = tid >> 5;
    const bool has2 = (384 + tid) < NCHUNK;   // tid < 198

    float d0[8], d1[8];
    {
        const float4* Dp4 = (const float4*)g_Dpk;
        float4 a = Dp4[tid * 2], b = Dp4[tid * 2 + 1];
        d0[0] = a.x; d0[1] = a.y; d0[2] = a.z; d0[3] = a.w;
        d0[4] = b.x; d0[5] = b.y; d0[6] = b.z; d0[7] = b.w;
        if (has2) {
            float4 a2 = Dp4[(384 + tid) * 2], b2 = Dp4[(384 + tid) * 2 + 1];
            d1[0] = a2.x; d1[1] = a2.y; d1[2] = a2.z; d1[3] = a2.w;
            d1[4] = b2.x; d1[5] = b2.y; d1[6] = b2.z; d1[7] = b2.w;
        }
    }

    const int row0 = blockIdx.x * 8;
    const H2x4* base = reinterpret_cast<const H2x4*>(g_M);
#pragma unroll 1
    for (int rp = 0; rp < 4; ++rp) {
        const H2x4* p0 = base + (size_t)(row0 + 2 * rp) * NCHUNK;
        const H2x4* p1 = p0 + NCHUNK;
        H2x4 m00 = p0[tid];
        H2x4 m10 = p1[tid];
        H2x4 m01, m11;
        if (has2) { m01 = p0[384 + tid]; m11 = p1[384 + tid]; }

        float a0 = h2x4_dot(m00, d0);
        float a1 = h2x4_dot(m10, d0);
        if (has2) {
            a0 += h2x4_dot(m01, d1);
            a1 += h2x4_dot(m11, d1);
        }
#pragma unroll
        for (int o = 16; o; o >>= 1) {
            a0 += __shfl_xor_sync(0xffffffffu, a0, o);
            a1 += __shfl_xor_sync(0xffffffffu, a1, o);
        }
        if (lane == 0) { sred_mv[(2 * rp) * 12 + wrp] = a0; sred_mv[(2 * rp + 1) * 12 + wrp] = a1; }
    }
    __syncthreads();
    if (tid < 8) {
        float s = 0.f;
#pragma unroll
        for (int w = 0; w < 12; ++w) s += sred_mv[tid * 12 + w];
        g_Fd[row0 + tid] = s;
    }
    __threadfence();
    __syncthreads();
    if (tid == 0) {
        unsigned old = atomicAdd(&g_cnt, 1u);
        if ((old % (unsigned)NCHUNK) == (unsigned)(NCHUNK - 1))
            atomicExch(&g_flag, 1u);   // release to solver block
    }
}

// ---------------------------------------------------------------------------
extern "C" void kernel_launch(void* const* d_in, const int* in_sizes, int n_in,
                              void* d_out, int out_size) {
    const float* mats[3] = {nullptr, nullptr, nullptr};
    int nm = 0;
    const float* G = nullptr;
    const float* Enuc = nullptr;
    for (int i = 0; i < n_in; ++i) {
        if (in_sizes[i] == N2) { if (nm < 3) mats[nm++] = (const float*)d_in[i]; }
        else if (in_sizes[i] == N4) G = (const float*)d_in[i];
        else if (in_sizes[i] == 1) Enuc = (const float*)d_in[i];
    }
    const float* H = mats[1];
    const float* A = mats[2];
    float* out = (float*)d_out;

    cudaFuncSetAttribute(build_M, cudaFuncAttributeMaxDynamicSharedMemorySize, BSM_BYTES);

    build_M<<<NPAIR, 256, BSM_BYTES>>>(G);
    solve_kernel<<<1, 384>>>(H, A, Enuc, out);
    for (int it = 1; it < NITERS_EFF; ++it) {
        fused_kernel<<<NCHUNK + 1, 384>>>(H, A, Enuc, out, it);
    }
}

// round 16
// speedup vs baseline: 1.2500x; 1.0452x over previous
#include <cuda_runtime.h>
#include <cuda_fp16.h>
#include <math.h>

#define NB     96
#define NP     97           // smem stride (conflict-free)
#define N2     (96*96)
#define N4     (96*96*96*96)
#define NPAIR  4656         // #(p<=q)
#define NCHUNK 582          // NPAIR/8 H2x4 chunks per row
#define MMAX   12
#define NITERS_EFF 4        // SCF steps (iters 0..3)

// persistent scratch (allowed: __device__ globals)
__device__ __half g_M[(size_t)NPAIR * NPAIR];  // 43.4 MB packed both ways
__device__ float  g_Fd[NPAIR];
__device__ float  g_c[NB];                     // occupied orbital (AO basis)
__device__ float  g_c2[NB];                    // warm-start vector
__device__ unsigned g_cnt;                     // completion counter (monotonic)
__device__ unsigned g_flag;                    // release flag for solver block

struct alignas(16) H2x4 { __half2 h[4]; };

__host__ __device__ __forceinline__ int pair_off(int p) {
    return p * 96 - (p * (p - 1)) / 2;   // index of (p,p) in packed order
}
__device__ __forceinline__ int pair_row(int t) {   // invert pair_off
    int r = (int)((193.0f - sqrtf(193.0f * 193.0f - 8.0f * (float)t)) * 0.5f);
    while (pair_off(r + 1) <= t) ++r;
    while (pair_off(r) > t) --r;
    return r;
}

// ---------------------------------------------------------------------------
// Register-operator matvec: dst = Reg-matrix * src (src in smem).
// thread = (row = tid>>2, part = tid&3); Reg holds Mat[row][part*24 .. +24].
// ---------------------------------------------------------------------------
__device__ __forceinline__ void opmv_reg(float* __restrict__ dst,
                                         const float (&Reg)[24],
                                         const float* __restrict__ src,
                                         int row, int jb, int part) {
    float s = 0.f;
#pragma unroll
    for (int j = 0; j < 24; ++j) s = fmaf(Reg[j], src[jb + j], s);
    s += __shfl_xor_sync(0xffffffffu, s, 1);
    s += __shfl_xor_sync(0xffffffffu, s, 2);
    if (part == 0) dst[row] = s;
}

// ---------------------------------------------------------------------------
// Shared-memory block for the solve (~7 KB)
// ---------------------------------------------------------------------------
struct SolveSmem {
    float sV[MMAX * NP];
    float sw[96], st1[96], st2[96];
    float sdots[96];
    float salpha[MMAX], sbeta[MMAX], sy[MMAX];
    float sc2[96], sc[96];
    float sctrl[16], sred[16];
};

// Initialize + normalize the Lanczos start vector in S->sV row 0.
__device__ void solve_prep(SolveSmem* S, int iter, int tid) {
    if (tid < 96) {
        float v;
        if (iter == 0) {
            unsigned h = (unsigned)tid * 2654435761u + 12345u;
            h ^= h >> 13; h *= 0x85ebca6bu; h ^= h >> 16;
            v = (float)(h & 0xFFFFu) * (1.f / 65536.f) - 0.5f;
        } else {
            v = g_c2[tid];
        }
        S->sV[tid] = v;
    }
    __syncthreads();
    if (tid < 32) {
        float s = S->sV[tid] * S->sV[tid] + S->sV[tid + 32] * S->sV[tid + 32]
                + S->sV[tid + 64] * S->sV[tid + 64];
#pragma unroll
        for (int o = 16; o; o >>= 1) s += __shfl_xor_sync(0xffffffffu, s, o);
        if (tid == 0) S->sctrl[0] = rsqrtf(fmaxf(s, 1e-30f));
    }
    __syncthreads();
    if (tid < 96) S->sV[tid] *= S->sctrl[0];
    __syncthreads();
}

// Lanczos loop -> eigvec -> g_c publish -> (final) energy.
__device__ void solve_tail(SolveSmem* S,
                           const float (&Areg)[24], const float (&Freg)[24],
                           const float* __restrict__ gEnuc,
                           float* __restrict__ out, int iter, int tid) {
    const int row = tid >> 2, part = tid & 3, jb = part * 24;
    const int m      = (iter == 0) ? 10 : ((iter == NITERS_EFF - 1) ? 8 : 4);
    const int passes = (iter == 0) ? 2 : 1;

    int meff = m;
    for (int k = 0; k < m; ++k) {
        opmv_reg(S->st1, Areg, S->sV + k * NP, row, jb, part);
        __syncthreads();
        opmv_reg(S->st2, Freg, S->st1, row, jb, part);
        __syncthreads();
        opmv_reg(S->sw, Areg, S->st2, row, jb, part);
        __syncthreads();

#pragma unroll 1
        for (int pass = 0; pass < passes; ++pass) {
            {
                const int j = tid >> 2;
                float s = 0.f;
                if (j <= k) {
#pragma unroll
                    for (int i = 0; i < 24; ++i)
                        s = fmaf(S->sV[j * NP + jb + i], S->sw[jb + i], s);
                }
                s += __shfl_xor_sync(0xffffffffu, s, 1);
                s += __shfl_xor_sync(0xffffffffu, s, 2);
                if (part == 0 && j <= k) S->sdots[j] = s;
            }
            __syncthreads();
            if (pass == 0 && tid == 0) S->salpha[k] = S->sdots[k];
            if (tid < 96) {
                float wi = S->sw[tid];
                for (int j = 0; j <= k; ++j) wi = fmaf(-S->sdots[j], S->sV[j * NP + tid], wi);
                S->sw[tid] = wi;
                if (pass == passes - 1) {
                    float s2 = wi * wi;
#pragma unroll
                    for (int o = 16; o; o >>= 1) s2 += __shfl_xor_sync(0xffffffffu, s2, o);
                    if ((tid & 31) == 0) S->sred[tid >> 5] = s2;
                }
            }
            __syncthreads();
        }

        const float b2   = S->sred[0] + S->sred[1] + S->sred[2];
        const float beta = sqrtf(fmaxf(b2, 0.f));
        if (tid == 0) S->sbeta[k] = beta;
        const float tol = 1e-6f * (fabsf(S->salpha[0]) + 1.f);
        if (beta < tol) { meff = k + 1; break; }
        if (k + 1 < m) {
            const float invb = rsqrtf(fmaxf(b2, 1e-38f));
            if (tid < 96) S->sV[(k + 1) * NP + tid] = S->sw[tid] * invb;
        }
        __syncthreads();
    }
    __syncthreads();

    // ---- lowest eigenvalue via 32-way Sturm bisection (4 rounds) ----
    if (tid < 32) {
        if (tid == 0) {
            float lo = 1e30f, hi = -1e30f;
            for (int i = 0; i < meff; ++i) {
                float r = (i > 0 ? fabsf(S->sbeta[i - 1]) : 0.f) +
                          (i < meff - 1 ? fabsf(S->sbeta[i]) : 0.f);
                lo = fminf(lo, S->salpha[i] - r);
                hi = fmaxf(hi, S->salpha[i] + r);
            }
            S->sctrl[2] = lo; S->sctrl[3] = hi;
        }
        __syncwarp();
        for (int round = 0; round < 4; ++round) {
            const float lo = S->sctrl[2], hi = S->sctrl[3];
            const float x = lo + (hi - lo) * (float)(tid + 1) * (1.f / 33.f);
            int cnt = 0;
            float dd = S->salpha[0] - x;
            if (dd < 0.f) cnt++;
            for (int i = 1; i < meff; ++i) {
                float ad = dd;
                if (fabsf(ad) < 1e-25f) ad = (ad < 0.f) ? -1e-25f : 1e-25f;
                dd = (S->salpha[i] - x) - __fdividef(S->sbeta[i - 1] * S->sbeta[i - 1], ad);
                if (dd < 0.f) cnt++;
            }
            const unsigned ball = __ballot_sync(0xffffffffu, cnt >= 1);
            if (tid == 0) {
                if (ball == 0u) {
                    S->sctrl[2] = lo + (hi - lo) * (32.f / 33.f);
                } else {
                    const int f = __ffs(ball) - 1;
                    S->sctrl[3] = lo + (hi - lo) * (float)(f + 1) * (1.f / 33.f);
                    if (f > 0) S->sctrl[2] = lo + (hi - lo) * (float)f * (1.f / 33.f);
                }
            }
            __syncwarp();
        }
        if (tid == 0) {  // inverse iteration, 2 Thomas sweeps
            const float lo = S->sctrl[2], hi = S->sctrl[3];
            const float sig = lo - 0.01f * (hi - lo) - 1e-6f;
            for (int i = 0; i < meff; ++i) S->sy[i] = 1.f;
            for (int itn = 0; itn < 2; ++itn) {
                float den = S->salpha[0] - sig;
                if (fabsf(den) < 1e-25f) den = 1e-25f;
                S->sdots[0] = (meff > 1) ? __fdividef(S->sbeta[0], den) : 0.f;
                S->sw[0] = __fdividef(S->sy[0], den);
                for (int i = 1; i < meff; ++i) {
                    float mden = (S->salpha[i] - sig) - S->sbeta[i - 1] * S->sdots[i - 1];
                    if (fabsf(mden) < 1e-25f) mden = 1e-25f;
                    S->sdots[i] = (i < meff - 1) ? __fdividef(S->sbeta[i], mden) : 0.f;
                    S->sw[i] = __fdividef(S->sy[i] - S->sbeta[i - 1] * S->sw[i - 1], mden);
                }
                S->sy[meff - 1] = S->sw[meff - 1];
                for (int i = meff - 2; i >= 0; --i) S->sy[i] = S->sw[i] - S->sdots[i] * S->sy[i + 1];
                float nn = 0.f;
                for (int i = 0; i < meff; ++i) nn += S->sy[i] * S->sy[i];
                const float inv = rsqrtf(fmaxf(nn, 1e-38f));
                for (int i = 0; i < meff; ++i) S->sy[i] *= inv;
            }
        }
    }
    __syncthreads();

    // ---- Ritz vector c2 = V^T y, normalize ----
    if (tid < 96) {
        float s = 0.f;
        for (int kk = 0; kk < meff; ++kk) s = fmaf(S->sy[kk], S->sV[kk * NP + tid], s);
        S->sc2[tid] = s;
    }
    __syncthreads();
    if (tid < 32) {
        float s = S->sc2[tid] * S->sc2[tid] + S->sc2[tid + 32] * S->sc2[tid + 32]
                + S->sc2[tid + 64] * S->sc2[tid + 64];
#pragma unroll
        for (int o = 16; o; o >>= 1) s += __shfl_xor_sync(0xffffffffu, s, o);
        if (tid == 0) S->sctrl[4] = rsqrtf(fmaxf(s, 1e-38f));
    }
    __syncthreads();
    if (tid < 96) S->sc2[tid] *= S->sctrl[4];
    __syncthreads();

    // ---- c = A * c2 (register A); publish c and c2 (NO Dpk writeback —
    //      next launch's matvec blocks compute c_i*c_j on the fly) ----
    opmv_reg(S->sc, Areg, S->sc2, row, jb, part);
    if (tid < 96) g_c2[tid] = S->sc2[tid];
    __syncthreads();
    if (tid < 96) g_c[tid] = S->sc[tid];

    // ---- energy on final iteration: E = 2*c^T F c - Fd.D + Enuc ----
    if (iter == NITERS_EFF - 1) {
        float e2 = 0.f;
        for (int t = tid; t < NPAIR; t += 384) {
            const int i = pair_row(t);
            const int j = i + (t - pair_off(i));
            e2 += g_Fd[t] * S->sc[i] * S->sc[j] * ((i == j) ? 1.f : 2.f);
        }
        float s = 0.f;
#pragma unroll
        for (int j = 0; j < 24; ++j) s = fmaf(Freg[j], S->sc[jb + j], s);
        float val = 2.f * S->sc[row] * s - e2;
#pragma unroll
        for (int o = 16; o; o >>= 1) val += __shfl_xor_sync(0xffffffffu, val, o);
        if ((tid & 31) == 0) S->sred[tid >> 5] = val;
        __syncthreads();
        if (tid == 0) {
            float e = 0.f;
#pragma unroll
            for (int w = 0; w < 12; ++w) e += S->sred[w];
            out[0] = e + gEnuc[0];
        }
    }
}

// ---------------------------------------------------------------------------
// Build packed M̃ (standalone, 256 threads — keeps its own low reg count):
//   C[r][s] = 2G[pqrs] - G[prqs]; M̃[row][(r,s)] = C[r][s] + (r<s ? C[s][r] : 0)
// ---------------------------------------------------------------------------
#define BSM_BYTES (96 * NP * 4)
__global__ __launch_bounds__(256) void build_M(const float* __restrict__ G) {
    extern __shared__ float tC[];

    const int row = blockIdx.x;            // 0..NPAIR-1, consecutive rows share p
    const int p = pair_row(row);
    const int q = p + (row - pair_off(p));

    const float* gAa = G + (size_t)(p * 96 + q) * 9216;
    for (int i4 = threadIdx.x; i4 < 2304; i4 += 256) {   // 96*96/4
        const int r  = i4 / 24;
        const int s0 = (i4 % 24) * 4;
        float4 a = *(const float4*)(gAa + r * 96 + s0);
        float4 b = *(const float4*)(G + ((size_t)((p * 96 + r) * 96 + q)) * 96 + s0);
        float* c = tC + r * NP + s0;
        c[0] = 2.f * a.x - b.x;
        c[1] = 2.f * a.y - b.y;
        c[2] = 2.f * a.z - b.z;
        c[3] = 2.f * a.w - b.w;
    }
    __syncthreads();

    H2x4* outp = reinterpret_cast<H2x4*>(g_M) + (size_t)row * NCHUNK;
    for (int c = threadIdx.x; c < NCHUNK; c += 256) {
        const int t0 = c * 8;
        int r = pair_row(t0);
        int s = r + (t0 - pair_off(r));
        __half hv[8];
#pragma unroll
        for (int u = 0; u < 8; ++u) {
            float v = tC[r * NP + s];
            if (s != r) v += tC[s * NP + r];
            hv[u] = __float2half_rn(v);
            if (++s > 95) { ++r; s = r; }
        }
        H2x4 o;
        o.h[0] = __halves2half2(hv[0], hv[1]);
        o.h[1] = __halves2half2(hv[2], hv[3]);
        o.h[2] = __halves2half2(hv[4], hv[5]);
        o.h[3] = __halves2half2(hv[6], hv[7]);
        outp[c] = o;
    }
}

// ---------------------------------------------------------------------------
// Standalone solve (iteration 0: F = H only)
// ---------------------------------------------------------------------------
__global__ __launch_bounds__(384) void solve_kernel(const float* __restrict__ gH,
                                                    const float* __restrict__ gA,
                                                    const float* __restrict__ gEnuc,
                                                    float* __restrict__ out) {
    __shared__ SolveSmem S;
    const int tid = threadIdx.x;
    const int row = tid >> 2, part = tid & 3, jb = part * 24;

    float Areg[24], Freg[24];
    const float* ga = gA + row * 96 + jb;
    const float* gh = gH + row * 96 + jb;
#pragma unroll
    for (int j = 0; j < 24; ++j) { Areg[j] = ga[j]; Freg[j] = gh[j]; }

    solve_prep(&S, 0, tid);
    solve_tail(&S, Areg, Freg, gEnuc, out, 0, tid);
}

// ---------------------------------------------------------------------------
// Fused: 582 matvec blocks + 1 DEDICATED solver block (blockIdx == NCHUNK).
// Matvec blocks reconstruct D on the fly: Dpk[(i,j)] = c_i * c_j from g_c.
// ---------------------------------------------------------------------------
__device__ __forceinline__ float h2x4_dot(const H2x4& m, const float* d) {
    float a = 0.f;
#pragma unroll
    for (int u = 0; u < 4; ++u) {
        float2 f = __half22float2(m.h[u]);
        a = fmaf(f.x, d[2 * u + 0], a);
        a = fmaf(f.y, d[2 * u + 1], a);
    }
    return a;
}

__global__ __launch_bounds__(384) void fused_kernel(const float* __restrict__ gH,
                                                    const float* __restrict__ gA,
                                                    const float* __restrict__ gEnuc,
                                                    float* __restrict__ out, int iter) {
    __shared__ SolveSmem S;
    const int tid = threadIdx.x;

    if (blockIdx.x == NCHUNK) {
        // ---- dedicated solver block ----
        const int row = tid >> 2, part = tid & 3, jb = part * 24;
        float Areg[24], Freg[24];
        const float* ga = gA + row * 96 + jb;
        const float* gh = gH + row * 96 + jb;
#pragma unroll
        for (int j = 0; j < 24; ++j) { Areg[j] = ga[j]; Freg[j] = gh[j]; }

        solve_prep(&S, iter, tid);   // warm-start vector (g_c2 from prev iter)

        if (tid == 0) {
            while (atomicAdd(&g_flag, 0u) == 0u) { __nanosleep(128); }
            atomicExch(&g_flag, 0u);   // reset for next launch (stream-ordered)
        }
        __syncthreads();
        __threadfence();               // acquire: all g_Fd writes visible

#pragma unroll
        for (int j = 0; j < 24; ++j) {
            const int col = jb + j;
            const int a = row < col ? row : col, b = row < col ? col : row;
            Freg[j] += g_Fd[pair_off(a) + (b - a)];
        }
        solve_tail(&S, Areg, Freg, gEnuc, out, iter, tid);
        return;
    }

    // ---- matvec blocks ----
    float* sred_mv = S.sV;               // overlay 8x12 reduce scratch
    float* sc = S.sc;                    // 96-float c vector
    const int lane = tid & 31, wrp = tid >> 5;
    const bool has2 = (384 + tid) < NCHUNK;   // tid < 198

    if (tid < 96) sc[tid] = g_c[tid];
    __syncthreads();

    // reconstruct this thread's packed D values: d[u] = c_i * c_j
    float d0[8], d1[8];
    {
        int t0 = tid * 8;
        int i = pair_row(t0), j = i + (t0 - pair_off(i));
#pragma unroll
        for (int u = 0; u < 8; ++u) {
            d0[u] = sc[i] * sc[j];
            if (++j > 95) { ++i; j = i; }
        }
        if (has2) {
            int t1 = (384 + tid) * 8;
            i = pair_row(t1); j = i + (t1 - pair_off(i));
#pragma unroll
            for (int u = 0; u < 8; ++u) {
                d1[u] = sc[i] * sc[j];
                if (++j > 95) { ++i; j = i; }
            }
        }
    }

    const int row0 = blockIdx.x * 8;
    const H2x4* base = reinterpret_cast<const H2x4*>(g_M);
#pragma unroll 1
    for (int rp = 0; rp < 4; ++rp) {
        const H2x4* p0 = base + (size_t)(row0 + 2 * rp) * NCHUNK;
        const H2x4* p1 = p0 + NCHUNK;
        H2x4 m00 = p0[tid];
        H2x4 m10 = p1[tid];
        H2x4 m01, m11;
        if (has2) { m01 = p0[384 + tid]; m11 = p1[384 + tid]; }

        float a0 = h2x4_dot(m00, d0);
        float a1 = h2x4_dot(m10, d0);
        if (has2) {
            a0 += h2x4_dot(m01, d1);
            a1 += h2x4_dot(m11, d1);
        }
#pragma unroll
        for (int o = 16; o; o >>= 1) {
            a0 += __shfl_xor_sync(0xffffffffu, a0, o);
            a1 += __shfl_xor_sync(0xffffffffu, a1, o);
        }
        if (lane == 0) { sred_mv[(2 * rp) * 12 + wrp] = a0; sred_mv[(2 * rp + 1) * 12 + wrp] = a1; }
    }
    __syncthreads();
    if (tid < 8) {
        float s = 0.f;
#pragma unroll
        for (int w = 0; w < 12; ++w) s += sred_mv[tid * 12 + w];
        g_Fd[row0 + tid] = s;
    }
    __threadfence();
    __syncthreads();
    if (tid == 0) {
        unsigned old = atomicAdd(&g_cnt, 1u);
        if ((old % (unsigned)NCHUNK) == (unsigned)(NCHUNK - 1))
            atomicExch(&g_flag, 1u);   // release to solver block
    }
}

// ---------------------------------------------------------------------------
extern "C" void kernel_launch(void* const* d_in, const int* in_sizes, int n_in,
                              void* d_out, int out_size) {
    const float* mats[3] = {nullptr, nullptr, nullptr};
    int nm = 0;
    const float* G = nullptr;
    const float* Enuc = nullptr;
    for (int i = 0; i < n_in; ++i) {
        if (in_sizes[i] == N2) { if (nm < 3) mats[nm++] = (const float*)d_in[i]; }
        else if (in_sizes[i] == N4) G = (const float*)d_in[i];
        else if (in_sizes[i] == 1) Enuc = (const float*)d_in[i];
    }
    const float* H = mats[1];
    const float* A = mats[2];
    float* out = (float*)d_out;

    cudaFuncSetAttribute(build_M, cudaFuncAttributeMaxDynamicSharedMemorySize, BSM_BYTES);

    build_M<<<NPAIR, 256, BSM_BYTES>>>(G);
    solve_kernel<<<1, 384>>>(H, A, Enuc, out);
    for (int it = 1; it < NITERS_EFF; ++it) {
        fused_kernel<<<NCHUNK + 1, 384>>>(H, A, Enuc, out, it);
    }
}